// round 14
// baseline (speedup 1.0000x reference)
#include <cuda_runtime.h>
#include <cuda_fp16.h>
#include <cstdint>

// Problem constants
#define BB 4
#define SS 2048
#define DD 1024
#define HH 16
#define HD 64
#define NT (BB * SS)        // 8192 tokens
#define D3 (3 * DD)         // 3072

#define WSC 64.0f           // weight scale 2^6
#define IWSC (1.0f / 64.0f)
#define QSCALE 0.1803368801f   // 0.125 * log2(e)

// ---------------------------------------------------------------------------
// Scratch (device globals — no runtime allocation)
// ---------------------------------------------------------------------------
static __device__ __half g_qkv[(size_t)NT * D3];
static __device__ __half g_x  [(size_t)NT * DD];
static __device__ __half g_a  [(size_t)NT * DD];
static __device__ __half g_wq [(size_t)D3 * DD];   // c_attn_w^T *64 [N][K]
static __device__ __half g_wp [(size_t)DD * DD];

// ---------------------------------------------------------------------------
__device__ __forceinline__ uint32_t smem_u32(const void* p) {
    uint32_t a;
    asm("{ .reg .u64 t; cvta.to.shared.u64 t, %1; cvt.u32.u64 %0, t; }" : "=r"(a) : "l"(p));
    return a;
}
__device__ __forceinline__ float ex2(float x) {
    float r;
    asm("ex2.approx.f32 %0, %1;" : "=f"(r) : "f"(x));
    return r;
}

#define CP_ASYNC16(saddr, gptr) \
    asm volatile("cp.async.cg.shared.global [%0], [%1], 16;" :: "r"(saddr), "l"(gptr) : "memory")
#define CP_COMMIT()  asm volatile("cp.async.commit_group;" ::: "memory")
#define CP_WAIT0()   asm volatile("cp.async.wait_group 0;" ::: "memory")
#define CP_WAIT1()   asm volatile("cp.async.wait_group 1;" ::: "memory")

#define LDMATRIX_X4(r0, r1, r2, r3, addr) \
    asm volatile("ldmatrix.sync.aligned.m8n8.x4.shared.b16 {%0,%1,%2,%3}, [%4];" \
        : "=r"(r0), "=r"(r1), "=r"(r2), "=r"(r3) : "r"(addr))

#define LDMATRIX_X4_T(r0, r1, r2, r3, addr) \
    asm volatile("ldmatrix.sync.aligned.m8n8.x4.trans.shared.b16 {%0,%1,%2,%3}, [%4];" \
        : "=r"(r0), "=r"(r1), "=r"(r2), "=r"(r3) : "r"(addr))

#define MMA_F16(c, a, b) \
    asm volatile("mma.sync.aligned.m16n8k16.row.col.f32.f16.f16.f32 " \
        "{%0,%1,%2,%3}, {%4,%5,%6,%7}, {%8,%9}, {%0,%1,%2,%3};" \
        : "+f"((c)[0]), "+f"((c)[1]), "+f"((c)[2]), "+f"((c)[3]) \
        : "r"((a)[0]), "r"((a)[1]), "r"((a)[2]), "r"((a)[3]), "r"((b)[0]), "r"((b)[1]))

__device__ __forceinline__ uint32_t pack_f16(float a, float b) {
    __half2 t = __floats2half2_rn(a, b);
    return *reinterpret_cast<uint32_t*>(&t);
}

// ---------------------------------------------------------------------------
// Conversion kernels
// ---------------------------------------------------------------------------
__global__ void act_h(const float4* __restrict__ x, uint2* __restrict__ o, int n4) {
    int i = blockIdx.x * blockDim.x + threadIdx.x;
    if (i >= n4) return;
    float4 v = x[i];
    uint2 r;
    r.x = pack_f16(v.x, v.y);
    r.y = pack_f16(v.z, v.w);
    o[i] = r;
}

// Both weight transposes in one launch.
__global__ void wt_both(const float* __restrict__ Wq, __half* __restrict__ oq,
                        const float* __restrict__ Wp, __half* __restrict__ op_) {
    __shared__ float t[32][33];
    const int K = DD;
    const float* W;
    __half* o;
    int N, bx = blockIdx.x;
    if (bx < 96) { W = Wq; o = oq; N = D3; }
    else         { W = Wp; o = op_; N = DD; bx -= 96; }
    const int kb = blockIdx.y * 32, nb = bx * 32;
    const int tx = threadIdx.x, ty = threadIdx.y;
#pragma unroll
    for (int i = 0; i < 32; i += 8)
        t[ty + i][tx] = W[(size_t)(kb + ty + i) * N + nb + tx];
    __syncthreads();
#pragma unroll
    for (int i = 0; i < 32; i += 8)
        o[(size_t)(nb + ty + i) * K + kb + tx] = __float2half_rn(t[tx][ty + i] * WSC);
}

// ---------------------------------------------------------------------------
// f16 HMMA GEMM v5 (QKV, frozen from R13): 128x64 CTA, 3 CTAs/SM.
// ---------------------------------------------------------------------------
#define GROWB 144
#define G6ATILE (128 * GROWB)          // 18432
#define G6BTILE (64 * GROWB)           // 9216
#define G6STAGE (G6ATILE + G6BTILE)    // 27648
#define G6SMEM  (2 * G6STAGE)          // 55296

extern __shared__ char g_dsmem[];

__global__ void __launch_bounds__(128, 3) gemm_mma64(
    const __half* __restrict__ A, const __half* __restrict__ B,
    const float* __restrict__ bias, __half* __restrict__ Ch,
    int M, int N, int K)
{
    const int tid  = threadIdx.x;
    const int wid  = tid >> 5;
    const int lane = tid & 31;
    const int wm   = wid >> 1;
    const int wn   = wid & 1;
    const int bm = blockIdx.y, bn = blockIdx.x;

    const __half* Ab = A + (size_t)(bm * 128) * K;
    const __half* Bb = B + (size_t)(bn * 64) * K;

    const uint32_t sb = smem_u32(g_dsmem);

    float acc[4][4][4];
#pragma unroll
    for (int i = 0; i < 4; i++)
#pragma unroll
        for (int j = 0; j < 4; j++)
#pragma unroll
            for (int v = 0; v < 4; v++) acc[i][j][v] = 0.0f;

    const int NS = K >> 6;

    auto load_stage = [&](int s, int buf) {
        const int k0 = s << 6;
        const uint32_t base = sb + buf * G6STAGE;
#pragma unroll
        for (int i = 0; i < 8; i++) {
            const int idx = i * 128 + tid;
            const int r = idx >> 3, c = idx & 7;
            CP_ASYNC16(base + r * GROWB + c * 16, Ab + (size_t)r * K + k0 + c * 8);
        }
#pragma unroll
        for (int i = 0; i < 4; i++) {
            const int idx = i * 128 + tid;
            const int r = idx >> 3, c = idx & 7;
            CP_ASYNC16(base + G6ATILE + r * GROWB + c * 16, Bb + (size_t)r * K + k0 + c * 8);
        }
        CP_COMMIT();
    };

    load_stage(0, 0);

    const int a_row  = (lane & 15);
    const int a_koff = (lane >> 4) * 16;
    const int b_blk  = lane >> 3;
    const int b_row8 = lane & 7;
    const int b_noff = ((b_blk >> 1) << 3) + b_row8;
    const int b_koff = (b_blk & 1) * 16;

    for (int s = 0; s < NS; s++) {
        CP_WAIT0();
        __syncthreads();
        if (s + 1 < NS) load_stage(s + 1, (s + 1) & 1);

        const uint32_t st = sb + (s & 1) * G6STAGE;
#pragma unroll
        for (int ks = 0; ks < 4; ks++) {
            const int kb = ks * 32;

            uint32_t af[4][4], bf[4][2];
#pragma unroll
            for (int mt = 0; mt < 4; mt++) {
                const uint32_t ar = st + (wm * 64 + mt * 16 + a_row) * GROWB + kb + a_koff;
                LDMATRIX_X4(af[mt][0], af[mt][1], af[mt][2], af[mt][3], ar);
            }
#pragma unroll
            for (int p = 0; p < 2; p++) {
                const uint32_t br = st + G6ATILE +
                    (wn * 32 + p * 16 + b_noff) * GROWB + kb + b_koff;
                LDMATRIX_X4(bf[2 * p][0], bf[2 * p][1], bf[2 * p + 1][0], bf[2 * p + 1][1], br);
            }
#pragma unroll
            for (int mt = 0; mt < 4; mt++)
#pragma unroll
                for (int nt = 0; nt < 4; nt++)
                    MMA_F16(acc[mt][nt], af[mt], bf[nt]);
        }
    }

    const int r0 = bm * 128 + wm * 64 + (lane >> 2);
    const int c0 = bn * 64 + wn * 32 + (lane & 3) * 2;
#pragma unroll
    for (int mt = 0; mt < 4; mt++)
#pragma unroll
        for (int nt = 0; nt < 4; nt++) {
            const int row = r0 + mt * 16;
            const int col = c0 + nt * 8;
            const float b0 = bias[col], b1 = bias[col + 1];
            *(uint32_t*)(Ch + (size_t)row * N + col) =
                pack_f16(acc[mt][nt][0] * IWSC + b0, acc[mt][nt][1] * IWSC + b1);
            *(uint32_t*)(Ch + (size_t)(row + 8) * N + col) =
                pack_f16(acc[mt][nt][2] * IWSC + b0, acc[mt][nt][3] * IWSC + b1);
        }
}

// ---------------------------------------------------------------------------
// f16 HMMA GEMM v4 (proj, frozen): 128x128 CTA, 2 CTAs/SM, fp32 output.
// ---------------------------------------------------------------------------
#define GATILE (128 * GROWB)           // 18432
#define GSTAGE (2 * GATILE)            // 36864
#define GSMEM  (3 * GSTAGE)            // 110592

__global__ void __launch_bounds__(128, 2) gemm_mma(
    const __half* __restrict__ A, const __half* __restrict__ B,
    const float* __restrict__ bias, float* __restrict__ Cf,
    int M, int N, int K)
{
    const int tid  = threadIdx.x;
    const int wid  = tid >> 5;
    const int lane = tid & 31;
    const int wm   = wid >> 1;
    const int wn   = wid & 1;
    const int bm = blockIdx.y, bn = blockIdx.x;

    const __half* Ab = A + (size_t)(bm * 128) * K;
    const __half* Bb = B + (size_t)(bn * 128) * K;

    const uint32_t sb = smem_u32(g_dsmem);

    float acc[4][8][4];
#pragma unroll
    for (int i = 0; i < 4; i++)
#pragma unroll
        for (int j = 0; j < 8; j++)
#pragma unroll
            for (int v = 0; v < 4; v++) acc[i][j][v] = 0.0f;

    const int NS = K >> 6;

    auto load_stage = [&](int s, int buf) {
        const int k0 = s << 6;
        const uint32_t base = sb + buf * GSTAGE;
#pragma unroll
        for (int i = 0; i < 8; i++) {
            const int idx = i * 128 + tid;
            const int r = idx >> 3, c = idx & 7;
            CP_ASYNC16(base + r * GROWB + c * 16, Ab + (size_t)r * K + k0 + c * 8);
        }
#pragma unroll
        for (int i = 0; i < 8; i++) {
            const int idx = i * 128 + tid;
            const int r = idx >> 3, c = idx & 7;
            CP_ASYNC16(base + GATILE + r * GROWB + c * 16, Bb + (size_t)r * K + k0 + c * 8);
        }
        CP_COMMIT();
    };

    load_stage(0, 0);
    load_stage(1, 1);

    const int a_row  = (lane & 15);
    const int a_koff = (lane >> 4) * 16;
    const int b_blk  = lane >> 3;
    const int b_row8 = lane & 7;
    const int b_noff = ((b_blk >> 1) << 3) + b_row8;
    const int b_koff = (b_blk & 1) * 16;

    for (int s = 0; s < NS; s++) {
        if (s < NS - 1) CP_WAIT1();
        else            CP_WAIT0();
        __syncthreads();
        if (s + 2 < NS) load_stage(s + 2, (s + 2) % 3);

        const uint32_t st = sb + (s % 3) * GSTAGE;
#pragma unroll
        for (int ks = 0; ks < 4; ks++) {
            const int kb = ks * 32;

            uint32_t af[4][4], bf[8][2];
#pragma unroll
            for (int mt = 0; mt < 4; mt++) {
                const uint32_t ar = st + (wm * 64 + mt * 16 + a_row) * GROWB + kb + a_koff;
                LDMATRIX_X4(af[mt][0], af[mt][1], af[mt][2], af[mt][3], ar);
            }
#pragma unroll
            for (int p = 0; p < 4; p++) {
                const uint32_t br = st + GATILE +
                    (wn * 64 + p * 16 + b_noff) * GROWB + kb + b_koff;
                LDMATRIX_X4(bf[2 * p][0], bf[2 * p][1], bf[2 * p + 1][0], bf[2 * p + 1][1], br);
            }
#pragma unroll
            for (int mt = 0; mt < 4; mt++)
#pragma unroll
                for (int nt = 0; nt < 8; nt++)
                    MMA_F16(acc[mt][nt], af[mt], bf[nt]);
        }
    }

    const int r0 = bm * 128 + wm * 64 + (lane >> 2);
    const int c0 = bn * 128 + wn * 64 + (lane & 3) * 2;
#pragma unroll
    for (int mt = 0; mt < 4; mt++)
#pragma unroll
        for (int nt = 0; nt < 8; nt++) {
            const int row = r0 + mt * 16;
            const int col = c0 + nt * 8;
            float2 o0, o1;
            o0.x = acc[mt][nt][0] * IWSC + bias[col];
            o0.y = acc[mt][nt][1] * IWSC + bias[col + 1];
            o1.x = acc[mt][nt][2] * IWSC + bias[col];
            o1.y = acc[mt][nt][3] * IWSC + bias[col + 1];
            *(float2*)(Cf + (size_t)row * N + col) = o0;
            *(float2*)(Cf + (size_t)(row + 8) * N + col) = o1;
        }
}

// ---------------------------------------------------------------------------
// Tensor-core causal flash attention v6: 4 warps x 32 q-rows (128 threads),
// K/V fragments amortized over 2 m16 blocks -> LDSM:MMA = 1:4 (GEMM parity).
// 64-key tiles, base-2 softmax, alpha-skip, 3-stage single-barrier ring,
// 2 CTAs/SM.
// ---------------------------------------------------------------------------
#define AROWB 144
#define ATILE (64 * AROWB)             // 9216
#define ASTAGE (2 * ATILE)             // 18432
#define ASMEM (3 * ASTAGE)             // 55296

__global__ void __launch_bounds__(128, 2) attn_mma(
    const __half* __restrict__ QKV, __half* __restrict__ O)
{
    const int tid  = threadIdx.x;
    const int wid  = tid >> 5;        // 0..3
    const int lane = tid & 31;
    const int qtile = (gridDim.x - 1) - blockIdx.x;   // heavy tiles first
    const int bh = blockIdx.y;
    const int b  = bh >> 4;
    const int h  = bh & 15;
    const int bS = b * SS;
    const int qbase = qtile * 128 + wid * 32;         // 32 q-rows per warp

    const uint32_t sb = smem_u32(g_dsmem);

    // stage Q (128 rows x 64 dims f16): 1024 chunks, 8/thread
#pragma unroll
    for (int i = 0; i < 8; i++) {
        const int idx = i * 128 + tid;
        const int r = idx >> 3, c = idx & 7;
        const size_t g = (size_t)(bS + qtile * 128 + r) * D3 + h * HD + c * 8;
        CP_ASYNC16(sb + r * AROWB + c * 16, QKV + g);
    }
    CP_COMMIT();
    CP_WAIT0();
    __syncthreads();

    // Q fragments for 2 m16 blocks, pre-scaled by 0.125*log2(e)
    uint32_t qf[2][4][4];
    const int a_row  = lane & 15;
    const int a_koff = (lane >> 4) * 16;
    {
        const __half2 qs = __float2half2_rn(QSCALE);
#pragma unroll
        for (int mb = 0; mb < 2; mb++) {
            const uint32_t qr = sb + (wid * 32 + mb * 16 + a_row) * AROWB + a_koff;
#pragma unroll
            for (int ks = 0; ks < 4; ks++) {
                LDMATRIX_X4(qf[mb][ks][0], qf[mb][ks][1], qf[mb][ks][2], qf[mb][ks][3],
                            qr + ks * 32);
#pragma unroll
                for (int j = 0; j < 4; j++) {
                    __half2 v = *reinterpret_cast<__half2*>(&qf[mb][ks][j]);
                    v = __hmul2(v, qs);
                    qf[mb][ks][j] = *reinterpret_cast<uint32_t*>(&v);
                }
            }
        }
    }
    __syncthreads();   // Q region reused for K/V ring

    // K/V tile loader: 1024 chunks, 8/thread
    auto load_kv = [&](int kt, int buf) {
        const int k0 = kt * 64;
        const uint32_t base = sb + buf * ASTAGE;
#pragma unroll
        for (int i = 0; i < 8; i++) {
            const int idx  = i * 128 + tid;     // 0..1023
            const int tile = idx >> 9;          // 0=K, 1=V
            const int r    = (idx >> 3) & 63;
            const int c    = idx & 7;
            const size_t g = (size_t)(bS + k0 + r) * D3 +
                             (tile ? 2 * DD : DD) + h * HD + c * 8;
            CP_ASYNC16(base + tile * ATILE + r * AROWB + c * 16, QKV + g);
        }
        CP_COMMIT();
    };

    float o[2][8][4];
#pragma unroll
    for (int mb = 0; mb < 2; mb++)
#pragma unroll
        for (int n = 0; n < 8; n++)
#pragma unroll
            for (int j = 0; j < 4; j++) o[mb][n][j] = 0.0f;
    float mrow[2][2] = {{-1e30f, -1e30f}, {-1e30f, -1e30f}};
    float lrow[2][2] = {{0.0f, 0.0f}, {0.0f, 0.0f}};

    const int b_blk  = lane >> 3;
    const int b_row8 = lane & 7;
    const int b_noff = ((b_blk >> 1) << 3) + b_row8;
    const int b_koff = (b_blk & 1) * 16;
    const int v_row  = lane & 15;
    const int v_coff = ((lane >> 4) & 1) * 16;

    const int ntl = 2 * qtile + 2;
    load_kv(0, 0);
    if (ntl > 1) load_kv(1, 1);

    for (int kt = 0; kt < ntl; kt++) {
        if (kt < ntl - 1) CP_WAIT1();
        else              CP_WAIT0();
        __syncthreads();
        if (kt + 2 < ntl) load_kv(kt + 2, (kt + 2) % 3);

        const int k0 = kt * 64;
        if (k0 <= qbase + 31) {     // warp has unmasked work
            const uint32_t kbse = sb + (kt % 3) * ASTAGE;
            const uint32_t vbse = kbse + ATILE;

            // S = Q K^T for both m16 blocks: each K LDSM feeds 4 MMAs
            float s[2][8][4];
#pragma unroll
            for (int mb = 0; mb < 2; mb++)
#pragma unroll
                for (int n = 0; n < 8; n++)
#pragma unroll
                    for (int j = 0; j < 4; j++) s[mb][n][j] = 0.0f;

#pragma unroll
            for (int p = 0; p < 4; p++) {
#pragma unroll
                for (int ks = 0; ks < 4; ks++) {
                    uint32_t kf[4];
                    const uint32_t ar = kbse + (p * 16 + b_noff) * AROWB + ks * 32 + b_koff;
                    LDMATRIX_X4(kf[0], kf[1], kf[2], kf[3], ar);
                    uint32_t b0[2] = {kf[0], kf[1]}, b1[2] = {kf[2], kf[3]};
                    MMA_F16(s[0][2 * p],     qf[0][ks], b0);
                    MMA_F16(s[0][2 * p + 1], qf[0][ks], b1);
                    MMA_F16(s[1][2 * p],     qf[1][ks], b0);
                    MMA_F16(s[1][2 * p + 1], qf[1][ks], b1);
                }
            }

            // masking + online softmax (base 2, alpha-skip) per m16 block
            const int colb = k0 + (lane & 3) * 2;
#pragma unroll
            for (int mb = 0; mb < 2; mb++) {
                const int rowb = qbase + mb * 16;
                const bool need_mask = (k0 + 63 > rowb);
#pragma unroll
                for (int hf = 0; hf < 2; hf++) {
                    const int row = rowb + (lane >> 2) + 8 * hf;
                    float mx = mrow[mb][hf];
                    if (need_mask) {
#pragma unroll
                        for (int n = 0; n < 8; n++) {
                            const int col = colb + 8 * n;
                            if (col > row)     s[mb][n][2 * hf]     = -1e30f;
                            if (col + 1 > row) s[mb][n][2 * hf + 1] = -1e30f;
                        }
                    }
#pragma unroll
                    for (int n = 0; n < 8; n++)
                        mx = fmaxf(mx, fmaxf(s[mb][n][2 * hf], s[mb][n][2 * hf + 1]));
                    mx = fmaxf(mx, __shfl_xor_sync(0xffffffffu, mx, 1));
                    mx = fmaxf(mx, __shfl_xor_sync(0xffffffffu, mx, 2));
                    if (mx > mrow[mb][hf]) {
                        const float alpha = ex2(mrow[mb][hf] - mx);
                        lrow[mb][hf] *= alpha;
#pragma unroll
                        for (int n = 0; n < 8; n++) {
                            o[mb][n][2 * hf]     *= alpha;
                            o[mb][n][2 * hf + 1] *= alpha;
                        }
                        mrow[mb][hf] = mx;
                    }
                    float ls = 0.0f;
#pragma unroll
                    for (int n = 0; n < 8; n++) {
                        const float p0 = ex2(s[mb][n][2 * hf]     - mx);
                        const float p1 = ex2(s[mb][n][2 * hf + 1] - mx);
                        s[mb][n][2 * hf] = p0; s[mb][n][2 * hf + 1] = p1;
                        ls += p0 + p1;
                    }
                    lrow[mb][hf] += ls;
                }
            }

            // O += P V: each V LDSM feeds 4 MMAs
#pragma unroll
            for (int ks = 0; ks < 4; ks++) {
                uint32_t pf[2][4];
#pragma unroll
                for (int mb = 0; mb < 2; mb++)
#pragma unroll
                    for (int q2 = 0; q2 < 2; q2++) {
                        const float* pv = s[mb][2 * ks + q2];
                        pf[mb][q2 * 2]     = pack_f16(pv[0], pv[1]);
                        pf[mb][q2 * 2 + 1] = pack_f16(pv[2], pv[3]);
                    }
#pragma unroll
                for (int np = 0; np < 4; np++) {
                    uint32_t vf[4];
                    const uint32_t va = vbse + (ks * 16 + v_row) * AROWB + np * 32 + v_coff;
                    LDMATRIX_X4_T(vf[0], vf[1], vf[2], vf[3], va);
                    uint32_t v0[2] = {vf[0], vf[1]}, v1[2] = {vf[2], vf[3]};
                    MMA_F16(o[0][2 * np],     pf[0], v0);
                    MMA_F16(o[0][2 * np + 1], pf[0], v1);
                    MMA_F16(o[1][2 * np],     pf[1], v0);
                    MMA_F16(o[1][2 * np + 1], pf[1], v1);
                }
            }
        }
    }

    // finalize both m16 blocks
    const int colb = h * HD + (lane & 3) * 2;
#pragma unroll
    for (int mb = 0; mb < 2; mb++) {
#pragma unroll
        for (int hf = 0; hf < 2; hf++) {
            float l = lrow[mb][hf];
            l += __shfl_xor_sync(0xffffffffu, l, 1);
            l += __shfl_xor_sync(0xffffffffu, l, 2);
            const float inv = 1.0f / l;
            const int row = qbase + mb * 16 + (lane >> 2) + 8 * hf;
            const size_t rof = (size_t)(bS + row) * DD;
#pragma unroll
            for (int n = 0; n < 8; n++)
                *(uint32_t*)(O + rof + colb + n * 8) =
                    pack_f16(o[mb][n][2 * hf] * inv, o[mb][n][2 * hf + 1] * inv);
        }
    }
}

// ---------------------------------------------------------------------------
extern "C" void kernel_launch(void* const* d_in, const int* in_sizes, int n_in,
                              void* d_out, int out_size)
{
    const float* hidden   = (const float*)d_in[0];
    const float* c_attn_w = (const float*)d_in[1];
    const float* c_attn_b = (const float*)d_in[2];
    const float* c_proj_w = (const float*)d_in[3];
    const float* c_proj_b = (const float*)d_in[4];
    float* out = (float*)d_out;

    __half *qkv, *x, *a, *wq, *wp;
    cudaGetSymbolAddress((void**)&qkv, g_qkv);
    cudaGetSymbolAddress((void**)&x,   g_x);
    cudaGetSymbolAddress((void**)&a,   g_a);
    cudaGetSymbolAddress((void**)&wq,  g_wq);
    cudaGetSymbolAddress((void**)&wp,  g_wp);

    cudaFuncSetAttribute(gemm_mma64, cudaFuncAttributeMaxDynamicSharedMemorySize, G6SMEM);
    cudaFuncSetAttribute(gemm_mma,   cudaFuncAttributeMaxDynamicSharedMemorySize, GSMEM);
    cudaFuncSetAttribute(attn_mma,   cudaFuncAttributeMaxDynamicSharedMemorySize, ASMEM);

    // prep
    {
        const int n4 = NT * DD / 4;
        act_h<<<(n4 + 255) / 256, 256>>>((const float4*)hidden, (uint2*)x, n4);
    }
    wt_both<<<dim3(128, DD / 32), dim3(32, 8)>>>(c_attn_w, wq, c_proj_w, wp);

    // 1) QKV projection -> f16
    gemm_mma64<<<dim3(D3 / 64, NT / 128), 128, G6SMEM>>>(
        x, wq, c_attn_b, qkv, NT, D3, DD);

    // 2) causal flash attention -> f16 (4 warps x 32 q-rows)
    attn_mma<<<dim3(SS / 128, BB * HH), 128, ASMEM>>>(qkv, a);

    // 3) output projection -> fp32
    gemm_mma<<<dim3(DD / 128, NT / 128), 128, GSMEM>>>(
        a, wp, c_proj_b, out, NT, DD, DD);
}

// round 15
// speedup vs baseline: 1.0348x; 1.0348x over previous
#include <cuda_runtime.h>
#include <cuda_fp16.h>
#include <cstdint>

// Problem constants
#define BB 4
#define SS 2048
#define DD 1024
#define HH 16
#define HD 64
#define NT (BB * SS)        // 8192 tokens
#define D3 (3 * DD)         // 3072

#define WSC 64.0f           // weight scale 2^6
#define IWSC (1.0f / 64.0f)
#define QSCALE 0.1803368801f   // 0.125 * log2(e)

// ---------------------------------------------------------------------------
// Scratch (device globals — no runtime allocation)
// ---------------------------------------------------------------------------
static __device__ __half g_qkv[(size_t)NT * D3];
static __device__ __half g_x  [(size_t)NT * DD];
static __device__ __half g_a  [(size_t)NT * DD];
static __device__ __half g_wq [(size_t)D3 * DD];   // c_attn_w^T *64 [N][K]
static __device__ __half g_wp [(size_t)DD * DD];

// ---------------------------------------------------------------------------
__device__ __forceinline__ uint32_t smem_u32(const void* p) {
    uint32_t a;
    asm("{ .reg .u64 t; cvta.to.shared.u64 t, %1; cvt.u32.u64 %0, t; }" : "=r"(a) : "l"(p));
    return a;
}
__device__ __forceinline__ float ex2(float x) {
    float r;
    asm("ex2.approx.f32 %0, %1;" : "=f"(r) : "f"(x));
    return r;
}

#define CP_ASYNC16(saddr, gptr) \
    asm volatile("cp.async.cg.shared.global [%0], [%1], 16;" :: "r"(saddr), "l"(gptr) : "memory")
#define CP_COMMIT()  asm volatile("cp.async.commit_group;" ::: "memory")
#define CP_WAIT0()   asm volatile("cp.async.wait_group 0;" ::: "memory")
#define CP_WAIT1()   asm volatile("cp.async.wait_group 1;" ::: "memory")

#define LDMATRIX_X4(r0, r1, r2, r3, addr) \
    asm volatile("ldmatrix.sync.aligned.m8n8.x4.shared.b16 {%0,%1,%2,%3}, [%4];" \
        : "=r"(r0), "=r"(r1), "=r"(r2), "=r"(r3) : "r"(addr))

#define LDMATRIX_X4_T(r0, r1, r2, r3, addr) \
    asm volatile("ldmatrix.sync.aligned.m8n8.x4.trans.shared.b16 {%0,%1,%2,%3}, [%4];" \
        : "=r"(r0), "=r"(r1), "=r"(r2), "=r"(r3) : "r"(addr))

#define MMA_F16(c, a, b) \
    asm volatile("mma.sync.aligned.m16n8k16.row.col.f32.f16.f16.f32 " \
        "{%0,%1,%2,%3}, {%4,%5,%6,%7}, {%8,%9}, {%0,%1,%2,%3};" \
        : "+f"((c)[0]), "+f"((c)[1]), "+f"((c)[2]), "+f"((c)[3]) \
        : "r"((a)[0]), "r"((a)[1]), "r"((a)[2]), "r"((a)[3]), "r"((b)[0]), "r"((b)[1]))

__device__ __forceinline__ uint32_t pack_f16(float a, float b) {
    __half2 t = __floats2half2_rn(a, b);
    return *reinterpret_cast<uint32_t*>(&t);
}

// ---------------------------------------------------------------------------
// Fused prep: activations -> f16, both weight transposes. One launch.
// blocks [0, NACT): act conversion (256 thr each, 1024 float4 per block)
// blocks [NACT, NACT+4096): weight transpose 32x32 tiles (32x8 thr layout)
// ---------------------------------------------------------------------------
#define NACT 2048   // 2048 blocks x 1024 float4 = 2M float4 = 8192x1024 floats

__global__ void prep_all(const float4* __restrict__ x, uint2* __restrict__ xo,
                         const float* __restrict__ Wq, __half* __restrict__ oq,
                         const float* __restrict__ Wp, __half* __restrict__ op_) {
    const int blk = blockIdx.x;
    if (blk < NACT) {
        const int base = blk * 1024;
#pragma unroll
        for (int i = 0; i < 4; i++) {
            const int idx = base + i * 256 + threadIdx.x;
            float4 v = x[idx];
            uint2 r;
            r.x = pack_f16(v.x, v.y);
            r.y = pack_f16(v.z, v.w);
            xo[idx] = r;
        }
        return;
    }
    // weight transpose part
    __shared__ float t[32][33];
    int wblk = blk - NACT;                 // 0..4095 = 128 x-tiles * 32 k-tiles
    const int K = DD;
    int bx = wblk & 127;                   // 0..127
    const int kb = (wblk >> 7) * 32;       // 0..31 -> k tile
    const float* W;
    __half* o;
    int N;
    if (bx < 96) { W = Wq; o = oq; N = D3; }
    else         { W = Wp; o = op_; N = DD; bx -= 96; }
    const int nb = bx * 32;
    const int tx = threadIdx.x & 31, ty = threadIdx.x >> 5;   // 32x8
#pragma unroll
    for (int i = 0; i < 32; i += 8)
        t[ty + i][tx] = W[(size_t)(kb + ty + i) * N + nb + tx];
    __syncthreads();
#pragma unroll
    for (int i = 0; i < 32; i += 8)
        o[(size_t)(nb + ty + i) * K + kb + tx] = __float2half_rn(t[tx][ty + i] * WSC);
}

// ---------------------------------------------------------------------------
// f16 HMMA GEMM v5 (QKV, frozen from R13): 128x64 CTA, 3 CTAs/SM.
// ---------------------------------------------------------------------------
#define GROWB 144
#define G6ATILE (128 * GROWB)          // 18432
#define G6BTILE (64 * GROWB)           // 9216
#define G6STAGE (G6ATILE + G6BTILE)    // 27648
#define G6SMEM  (2 * G6STAGE)          // 55296

extern __shared__ char g_dsmem[];

__global__ void __launch_bounds__(128, 3) gemm_mma64(
    const __half* __restrict__ A, const __half* __restrict__ B,
    const float* __restrict__ bias, __half* __restrict__ Ch,
    int M, int N, int K)
{
    const int tid  = threadIdx.x;
    const int wid  = tid >> 5;
    const int lane = tid & 31;
    const int wm   = wid >> 1;
    const int wn   = wid & 1;
    const int bm = blockIdx.y, bn = blockIdx.x;

    const __half* Ab = A + (size_t)(bm * 128) * K;
    const __half* Bb = B + (size_t)(bn * 64) * K;

    const uint32_t sb = smem_u32(g_dsmem);

    float acc[4][4][4];
#pragma unroll
    for (int i = 0; i < 4; i++)
#pragma unroll
        for (int j = 0; j < 4; j++)
#pragma unroll
            for (int v = 0; v < 4; v++) acc[i][j][v] = 0.0f;

    const int NS = K >> 6;

    auto load_stage = [&](int s, int buf) {
        const int k0 = s << 6;
        const uint32_t base = sb + buf * G6STAGE;
#pragma unroll
        for (int i = 0; i < 8; i++) {
            const int idx = i * 128 + tid;
            const int r = idx >> 3, c = idx & 7;
            CP_ASYNC16(base + r * GROWB + c * 16, Ab + (size_t)r * K + k0 + c * 8);
        }
#pragma unroll
        for (int i = 0; i < 4; i++) {
            const int idx = i * 128 + tid;
            const int r = idx >> 3, c = idx & 7;
            CP_ASYNC16(base + G6ATILE + r * GROWB + c * 16, Bb + (size_t)r * K + k0 + c * 8);
        }
        CP_COMMIT();
    };

    load_stage(0, 0);

    const int a_row  = (lane & 15);
    const int a_koff = (lane >> 4) * 16;
    const int b_blk  = lane >> 3;
    const int b_row8 = lane & 7;
    const int b_noff = ((b_blk >> 1) << 3) + b_row8;
    const int b_koff = (b_blk & 1) * 16;

    for (int s = 0; s < NS; s++) {
        CP_WAIT0();
        __syncthreads();
        if (s + 1 < NS) load_stage(s + 1, (s + 1) & 1);

        const uint32_t st = sb + (s & 1) * G6STAGE;
#pragma unroll
        for (int ks = 0; ks < 4; ks++) {
            const int kb = ks * 32;

            uint32_t af[4][4], bf[4][2];
#pragma unroll
            for (int mt = 0; mt < 4; mt++) {
                const uint32_t ar = st + (wm * 64 + mt * 16 + a_row) * GROWB + kb + a_koff;
                LDMATRIX_X4(af[mt][0], af[mt][1], af[mt][2], af[mt][3], ar);
            }
#pragma unroll
            for (int p = 0; p < 2; p++) {
                const uint32_t br = st + G6ATILE +
                    (wn * 32 + p * 16 + b_noff) * GROWB + kb + b_koff;
                LDMATRIX_X4(bf[2 * p][0], bf[2 * p][1], bf[2 * p + 1][0], bf[2 * p + 1][1], br);
            }
#pragma unroll
            for (int mt = 0; mt < 4; mt++)
#pragma unroll
                for (int nt = 0; nt < 4; nt++)
                    MMA_F16(acc[mt][nt], af[mt], bf[nt]);
        }
    }

    const int r0 = bm * 128 + wm * 64 + (lane >> 2);
    const int c0 = bn * 64 + wn * 32 + (lane & 3) * 2;
#pragma unroll
    for (int mt = 0; mt < 4; mt++)
#pragma unroll
        for (int nt = 0; nt < 4; nt++) {
            const int row = r0 + mt * 16;
            const int col = c0 + nt * 8;
            const float b0 = bias[col], b1 = bias[col + 1];
            *(uint32_t*)(Ch + (size_t)row * N + col) =
                pack_f16(acc[mt][nt][0] * IWSC + b0, acc[mt][nt][1] * IWSC + b1);
            *(uint32_t*)(Ch + (size_t)(row + 8) * N + col) =
                pack_f16(acc[mt][nt][2] * IWSC + b0, acc[mt][nt][3] * IWSC + b1);
        }
}

// ---------------------------------------------------------------------------
// f16 HMMA GEMM v4 (proj, frozen): 128x128 CTA, 2 CTAs/SM, fp32 output.
// ---------------------------------------------------------------------------
#define GATILE (128 * GROWB)           // 18432
#define GSTAGE (2 * GATILE)            // 36864
#define GSMEM  (3 * GSTAGE)            // 110592

__global__ void __launch_bounds__(128, 2) gemm_mma(
    const __half* __restrict__ A, const __half* __restrict__ B,
    const float* __restrict__ bias, float* __restrict__ Cf,
    int M, int N, int K)
{
    const int tid  = threadIdx.x;
    const int wid  = tid >> 5;
    const int lane = tid & 31;
    const int wm   = wid >> 1;
    const int wn   = wid & 1;
    const int bm = blockIdx.y, bn = blockIdx.x;

    const __half* Ab = A + (size_t)(bm * 128) * K;
    const __half* Bb = B + (size_t)(bn * 128) * K;

    const uint32_t sb = smem_u32(g_dsmem);

    float acc[4][8][4];
#pragma unroll
    for (int i = 0; i < 4; i++)
#pragma unroll
        for (int j = 0; j < 8; j++)
#pragma unroll
            for (int v = 0; v < 4; v++) acc[i][j][v] = 0.0f;

    const int NS = K >> 6;

    auto load_stage = [&](int s, int buf) {
        const int k0 = s << 6;
        const uint32_t base = sb + buf * GSTAGE;
#pragma unroll
        for (int i = 0; i < 8; i++) {
            const int idx = i * 128 + tid;
            const int r = idx >> 3, c = idx & 7;
            CP_ASYNC16(base + r * GROWB + c * 16, Ab + (size_t)r * K + k0 + c * 8);
        }
#pragma unroll
        for (int i = 0; i < 8; i++) {
            const int idx = i * 128 + tid;
            const int r = idx >> 3, c = idx & 7;
            CP_ASYNC16(base + GATILE + r * GROWB + c * 16, Bb + (size_t)r * K + k0 + c * 8);
        }
        CP_COMMIT();
    };

    load_stage(0, 0);
    load_stage(1, 1);

    const int a_row  = (lane & 15);
    const int a_koff = (lane >> 4) * 16;
    const int b_blk  = lane >> 3;
    const int b_row8 = lane & 7;
    const int b_noff = ((b_blk >> 1) << 3) + b_row8;
    const int b_koff = (b_blk & 1) * 16;

    for (int s = 0; s < NS; s++) {
        if (s < NS - 1) CP_WAIT1();
        else            CP_WAIT0();
        __syncthreads();
        if (s + 2 < NS) load_stage(s + 2, (s + 2) % 3);

        const uint32_t st = sb + (s % 3) * GSTAGE;
#pragma unroll
        for (int ks = 0; ks < 4; ks++) {
            const int kb = ks * 32;

            uint32_t af[4][4], bf[8][2];
#pragma unroll
            for (int mt = 0; mt < 4; mt++) {
                const uint32_t ar = st + (wm * 64 + mt * 16 + a_row) * GROWB + kb + a_koff;
                LDMATRIX_X4(af[mt][0], af[mt][1], af[mt][2], af[mt][3], ar);
            }
#pragma unroll
            for (int p = 0; p < 4; p++) {
                const uint32_t br = st + GATILE +
                    (wn * 64 + p * 16 + b_noff) * GROWB + kb + b_koff;
                LDMATRIX_X4(bf[2 * p][0], bf[2 * p][1], bf[2 * p + 1][0], bf[2 * p + 1][1], br);
            }
#pragma unroll
            for (int mt = 0; mt < 4; mt++)
#pragma unroll
                for (int nt = 0; nt < 8; nt++)
                    MMA_F16(acc[mt][nt], af[mt], bf[nt]);
        }
    }

    const int r0 = bm * 128 + wm * 64 + (lane >> 2);
    const int c0 = bn * 128 + wn * 64 + (lane & 3) * 2;
#pragma unroll
    for (int mt = 0; mt < 4; mt++)
#pragma unroll
        for (int nt = 0; nt < 8; nt++) {
            const int row = r0 + mt * 16;
            const int col = c0 + nt * 8;
            float2 o0, o1;
            o0.x = acc[mt][nt][0] * IWSC + bias[col];
            o0.y = acc[mt][nt][1] * IWSC + bias[col + 1];
            o1.x = acc[mt][nt][2] * IWSC + bias[col];
            o1.y = acc[mt][nt][3] * IWSC + bias[col + 1];
            *(float2*)(Cf + (size_t)row * N + col) = o0;
            *(float2*)(Cf + (size_t)(row + 8) * N + col) = o1;
        }
}

// ---------------------------------------------------------------------------
// Tensor-core causal flash attention v7: 128 threads, 4 warps x 16 q-rows
// (64 q-rows/CTA), 64-key tiles, base-2 softmax + alpha-skip, 3-stage
// single-barrier ring, 4 CTAs/SM (4 independent barrier domains).
// ---------------------------------------------------------------------------
#define AROWB 144
#define ATILE (64 * AROWB)             // 9216
#define ASTAGE (2 * ATILE)             // 18432
#define ASMEM (3 * ASTAGE)             // 55296  (x4 CTAs = 221184 <= 228KB)

__global__ void __launch_bounds__(128, 4) attn_mma(
    const __half* __restrict__ QKV, __half* __restrict__ O)
{
    const int tid  = threadIdx.x;
    const int wid  = tid >> 5;        // 0..3
    const int lane = tid & 31;
    const int qtile = (gridDim.x - 1) - blockIdx.x;   // heavy tiles first
    const int bh = blockIdx.y;
    const int b  = bh >> 4;
    const int h  = bh & 15;
    const int bS = b * SS;
    const int qrow0 = qtile * 64;                     // CTA covers 64 q-rows
    const int qbase = qrow0 + wid * 16;

    const uint32_t sb = smem_u32(g_dsmem);

    // stage Q (64 rows x 64 dims f16): 512 chunks, 4/thread
#pragma unroll
    for (int i = 0; i < 4; i++) {
        const int idx = i * 128 + tid;
        const int r = idx >> 3, c = idx & 7;
        const size_t g = (size_t)(bS + qrow0 + r) * D3 + h * HD + c * 8;
        CP_ASYNC16(sb + r * AROWB + c * 16, QKV + g);
    }
    CP_COMMIT();
    CP_WAIT0();
    __syncthreads();

    // Q fragments, pre-scaled by 0.125*log2(e)
    uint32_t qf[4][4];
    const int a_row  = lane & 15;
    const int a_koff = (lane >> 4) * 16;
    {
        const uint32_t qr = sb + (wid * 16 + a_row) * AROWB + a_koff;
        const __half2 qs = __float2half2_rn(QSCALE);
#pragma unroll
        for (int ks = 0; ks < 4; ks++) {
            LDMATRIX_X4(qf[ks][0], qf[ks][1], qf[ks][2], qf[ks][3], qr + ks * 32);
#pragma unroll
            for (int j = 0; j < 4; j++) {
                __half2 v = *reinterpret_cast<__half2*>(&qf[ks][j]);
                v = __hmul2(v, qs);
                qf[ks][j] = *reinterpret_cast<uint32_t*>(&v);
            }
        }
    }
    __syncthreads();   // Q region reused for K/V ring

    // K/V tile loader: 1024 chunks, 8/thread
    auto load_kv = [&](int kt, int buf) {
        const int k0 = kt * 64;
        const uint32_t base = sb + buf * ASTAGE;
#pragma unroll
        for (int i = 0; i < 8; i++) {
            const int idx  = i * 128 + tid;
            const int tile = idx >> 9;
            const int r    = (idx >> 3) & 63;
            const int c    = idx & 7;
            const size_t g = (size_t)(bS + k0 + r) * D3 +
                             (tile ? 2 * DD : DD) + h * HD + c * 8;
            CP_ASYNC16(base + tile * ATILE + r * AROWB + c * 16, QKV + g);
        }
        CP_COMMIT();
    };

    float o[8][4];
#pragma unroll
    for (int n = 0; n < 8; n++)
#pragma unroll
        for (int j = 0; j < 4; j++) o[n][j] = 0.0f;
    float mrow[2] = {-1e30f, -1e30f};
    float lrow[2] = {0.0f, 0.0f};

    const int b_blk  = lane >> 3;
    const int b_row8 = lane & 7;
    const int b_noff = ((b_blk >> 1) << 3) + b_row8;
    const int b_koff = (b_blk & 1) * 16;
    const int v_row  = lane & 15;
    const int v_coff = ((lane >> 4) & 1) * 16;

    const int ntl = qtile + 1;       // 64-key tiles up to & incl. diagonal
    load_kv(0, 0);
    if (ntl > 1) load_kv(1, 1);

    for (int kt = 0; kt < ntl; kt++) {
        if (kt < ntl - 1) CP_WAIT1();
        else              CP_WAIT0();
        __syncthreads();
        if (kt + 2 < ntl) load_kv(kt + 2, (kt + 2) % 3);

        const int k0 = kt * 64;
        if (k0 <= qbase + 15) {
            const uint32_t kbse = sb + (kt % 3) * ASTAGE;
            const uint32_t vbse = kbse + ATILE;

            // S = Q K^T (base-2 logits)
            float s[8][4];
#pragma unroll
            for (int n = 0; n < 8; n++)
#pragma unroll
                for (int j = 0; j < 4; j++) s[n][j] = 0.0f;

#pragma unroll
            for (int p = 0; p < 4; p++) {
#pragma unroll
                for (int ks = 0; ks < 4; ks++) {
                    uint32_t kf[4];
                    const uint32_t ar = kbse + (p * 16 + b_noff) * AROWB + ks * 32 + b_koff;
                    LDMATRIX_X4(kf[0], kf[1], kf[2], kf[3], ar);
                    uint32_t b0[2] = {kf[0], kf[1]}, b1[2] = {kf[2], kf[3]};
                    MMA_F16(s[2 * p],     qf[ks], b0);
                    MMA_F16(s[2 * p + 1], qf[ks], b1);
                }
            }

            // masking + online softmax (base 2, alpha-skip)
            const bool need_mask = (k0 + 63 > qbase);
            const int row0 = qbase + (lane >> 2);
            const int colb = k0 + (lane & 3) * 2;
#pragma unroll
            for (int hf = 0; hf < 2; hf++) {
                const int row = row0 + 8 * hf;
                float mx = mrow[hf];
                if (need_mask) {
#pragma unroll
                    for (int n = 0; n < 8; n++) {
                        const int col = colb + 8 * n;
                        if (col > row)     s[n][2 * hf]     = -1e30f;
                        if (col + 1 > row) s[n][2 * hf + 1] = -1e30f;
                    }
                }
#pragma unroll
                for (int n = 0; n < 8; n++)
                    mx = fmaxf(mx, fmaxf(s[n][2 * hf], s[n][2 * hf + 1]));
                mx = fmaxf(mx, __shfl_xor_sync(0xffffffffu, mx, 1));
                mx = fmaxf(mx, __shfl_xor_sync(0xffffffffu, mx, 2));
                if (mx > mrow[hf]) {
                    const float alpha = ex2(mrow[hf] - mx);
                    lrow[hf] *= alpha;
#pragma unroll
                    for (int n = 0; n < 8; n++) {
                        o[n][2 * hf]     *= alpha;
                        o[n][2 * hf + 1] *= alpha;
                    }
                    mrow[hf] = mx;
                }
                float ls = 0.0f;
#pragma unroll
                for (int n = 0; n < 8; n++) {
                    const float p0 = ex2(s[n][2 * hf]     - mx);
                    const float p1 = ex2(s[n][2 * hf + 1] - mx);
                    s[n][2 * hf] = p0; s[n][2 * hf + 1] = p1;
                    ls += p0 + p1;
                }
                lrow[hf] += ls;
            }

            // O += P V
#pragma unroll
            for (int ks = 0; ks < 4; ks++) {
                uint32_t pf[4];
#pragma unroll
                for (int q2 = 0; q2 < 2; q2++) {
                    const float* pv = s[2 * ks + q2];
                    pf[q2 * 2]     = pack_f16(pv[0], pv[1]);
                    pf[q2 * 2 + 1] = pack_f16(pv[2], pv[3]);
                }
#pragma unroll
                for (int np = 0; np < 4; np++) {
                    uint32_t vf[4];
                    const uint32_t va = vbse + (ks * 16 + v_row) * AROWB + np * 32 + v_coff;
                    LDMATRIX_X4_T(vf[0], vf[1], vf[2], vf[3], va);
                    uint32_t v0[2] = {vf[0], vf[1]}, v1[2] = {vf[2], vf[3]};
                    MMA_F16(o[2 * np],     pf, v0);
                    MMA_F16(o[2 * np + 1], pf, v1);
                }
            }
        }
    }

    float inv[2];
#pragma unroll
    for (int hf = 0; hf < 2; hf++) {
        float l = lrow[hf];
        l += __shfl_xor_sync(0xffffffffu, l, 1);
        l += __shfl_xor_sync(0xffffffffu, l, 2);
        inv[hf] = 1.0f / l;
    }
    const int row0 = qbase + (lane >> 2);
    const int colb = h * HD + (lane & 3) * 2;
#pragma unroll
    for (int hf = 0; hf < 2; hf++) {
        const size_t rof = (size_t)(bS + row0 + 8 * hf) * DD;
#pragma unroll
        for (int n = 0; n < 8; n++)
            *(uint32_t*)(O + rof + colb + n * 8) =
                pack_f16(o[n][2 * hf] * inv[hf], o[n][2 * hf + 1] * inv[hf]);
    }
}

// ---------------------------------------------------------------------------
extern "C" void kernel_launch(void* const* d_in, const int* in_sizes, int n_in,
                              void* d_out, int out_size)
{
    const float* hidden   = (const float*)d_in[0];
    const float* c_attn_w = (const float*)d_in[1];
    const float* c_attn_b = (const float*)d_in[2];
    const float* c_proj_w = (const float*)d_in[3];
    const float* c_proj_b = (const float*)d_in[4];
    float* out = (float*)d_out;

    __half *qkv, *x, *a, *wq, *wp;
    cudaGetSymbolAddress((void**)&qkv, g_qkv);
    cudaGetSymbolAddress((void**)&x,   g_x);
    cudaGetSymbolAddress((void**)&a,   g_a);
    cudaGetSymbolAddress((void**)&wq,  g_wq);
    cudaGetSymbolAddress((void**)&wp,  g_wp);

    cudaFuncSetAttribute(gemm_mma64, cudaFuncAttributeMaxDynamicSharedMemorySize, G6SMEM);
    cudaFuncSetAttribute(gemm_mma,   cudaFuncAttributeMaxDynamicSharedMemorySize, GSMEM);
    cudaFuncSetAttribute(attn_mma,   cudaFuncAttributeMaxDynamicSharedMemorySize, ASMEM);

    // prep: one fused launch (act conversion + both weight transposes)
    prep_all<<<NACT + 4096, 256>>>((const float4*)hidden, (uint2*)x,
                                   c_attn_w, wq, c_proj_w, wp);

    // 1) QKV projection -> f16
    gemm_mma64<<<dim3(D3 / 64, NT / 128), 128, G6SMEM>>>(
        x, wq, c_attn_b, qkv, NT, D3, DD);

    // 2) causal flash attention -> f16 (64 q-rows/CTA, 4 CTAs/SM)
    attn_mma<<<dim3(SS / 64, BB * HH), 128, ASMEM>>>(qkv, a);

    // 3) output projection -> fp32
    gemm_mma<<<dim3(DD / 128, NT / 128), 128, GSMEM>>>(
        a, wp, c_proj_b, out, NT, DD, DD);
}

// round 16
// speedup vs baseline: 1.0511x; 1.0158x over previous
#include <cuda_runtime.h>
#include <cuda_fp16.h>
#include <cstdint>

// Problem constants
#define BB 4
#define SS 2048
#define DD 1024
#define HH 16
#define HD 64
#define NT (BB * SS)        // 8192 tokens
#define D3 (3 * DD)         // 3072

#define WSC 64.0f           // weight scale 2^6
#define IWSC (1.0f / 64.0f)
#define QSCALE 0.1803368801f   // 0.125 * log2(e)

// ---------------------------------------------------------------------------
// Scratch (device globals — no runtime allocation)
// ---------------------------------------------------------------------------
static __device__ __half g_qkv[(size_t)NT * D3];
static __device__ __half g_x  [(size_t)NT * DD];
static __device__ __half g_a  [(size_t)NT * DD];
static __device__ __half g_wq [(size_t)D3 * DD];   // c_attn_w^T *64 [N][K]
static __device__ __half g_wp [(size_t)DD * DD];

// ---------------------------------------------------------------------------
__device__ __forceinline__ uint32_t smem_u32(const void* p) {
    uint32_t a;
    asm("{ .reg .u64 t; cvta.to.shared.u64 t, %1; cvt.u32.u64 %0, t; }" : "=r"(a) : "l"(p));
    return a;
}
__device__ __forceinline__ float ex2(float x) {
    float r;
    asm("ex2.approx.f32 %0, %1;" : "=f"(r) : "f"(x));
    return r;
}

#define CP_ASYNC16(saddr, gptr) \
    asm volatile("cp.async.cg.shared.global [%0], [%1], 16;" :: "r"(saddr), "l"(gptr) : "memory")
#define CP_COMMIT()  asm volatile("cp.async.commit_group;" ::: "memory")
#define CP_WAIT0()   asm volatile("cp.async.wait_group 0;" ::: "memory")
#define CP_WAIT1()   asm volatile("cp.async.wait_group 1;" ::: "memory")

#define LDMATRIX_X4(r0, r1, r2, r3, addr) \
    asm volatile("ldmatrix.sync.aligned.m8n8.x4.shared.b16 {%0,%1,%2,%3}, [%4];" \
        : "=r"(r0), "=r"(r1), "=r"(r2), "=r"(r3) : "r"(addr))

#define LDMATRIX_X4_T(r0, r1, r2, r3, addr) \
    asm volatile("ldmatrix.sync.aligned.m8n8.x4.trans.shared.b16 {%0,%1,%2,%3}, [%4];" \
        : "=r"(r0), "=r"(r1), "=r"(r2), "=r"(r3) : "r"(addr))

#define MMA_F16(c, a, b) \
    asm volatile("mma.sync.aligned.m16n8k16.row.col.f32.f16.f16.f32 " \
        "{%0,%1,%2,%3}, {%4,%5,%6,%7}, {%8,%9}, {%0,%1,%2,%3};" \
        : "+f"((c)[0]), "+f"((c)[1]), "+f"((c)[2]), "+f"((c)[3]) \
        : "r"((a)[0]), "r"((a)[1]), "r"((a)[2]), "r"((a)[3]), "r"((b)[0]), "r"((b)[1]))

__device__ __forceinline__ uint32_t pack_f16(float a, float b) {
    __half2 t = __floats2half2_rn(a, b);
    return *reinterpret_cast<uint32_t*>(&t);
}

// ---------------------------------------------------------------------------
// Fused prep: activations -> f16, both weight transposes. One launch.
// ---------------------------------------------------------------------------
#define NACT 2048

__global__ void prep_all(const float4* __restrict__ x, uint2* __restrict__ xo,
                         const float* __restrict__ Wq, __half* __restrict__ oq,
                         const float* __restrict__ Wp, __half* __restrict__ op_) {
    const int blk = blockIdx.x;
    if (blk < NACT) {
        const int base = blk * 1024;
#pragma unroll
        for (int i = 0; i < 4; i++) {
            const int idx = base + i * 256 + threadIdx.x;
            float4 v = x[idx];
            uint2 r;
            r.x = pack_f16(v.x, v.y);
            r.y = pack_f16(v.z, v.w);
            xo[idx] = r;
        }
        return;
    }
    __shared__ float t[32][33];
    int wblk = blk - NACT;
    const int K = DD;
    int bx = wblk & 127;
    const int kb = (wblk >> 7) * 32;
    const float* W;
    __half* o;
    int N;
    if (bx < 96) { W = Wq; o = oq; N = D3; }
    else         { W = Wp; o = op_; N = DD; bx -= 96; }
    const int nb = bx * 32;
    const int tx = threadIdx.x & 31, ty = threadIdx.x >> 5;
#pragma unroll
    for (int i = 0; i < 32; i += 8)
        t[ty + i][tx] = W[(size_t)(kb + ty + i) * N + nb + tx];
    __syncthreads();
#pragma unroll
    for (int i = 0; i < 32; i += 8)
        o[(size_t)(nb + ty + i) * K + kb + tx] = __float2half_rn(t[tx][ty + i] * WSC);
}

// ---------------------------------------------------------------------------
// f16 HMMA GEMM v5 (QKV, frozen): 128x64 CTA, 3 CTAs/SM.
// ---------------------------------------------------------------------------
#define GROWB 144
#define G6ATILE (128 * GROWB)
#define G6BTILE (64 * GROWB)
#define G6STAGE (G6ATILE + G6BTILE)
#define G6SMEM  (2 * G6STAGE)

extern __shared__ char g_dsmem[];

__global__ void __launch_bounds__(128, 3) gemm_mma64(
    const __half* __restrict__ A, const __half* __restrict__ B,
    const float* __restrict__ bias, __half* __restrict__ Ch,
    int M, int N, int K)
{
    const int tid  = threadIdx.x;
    const int wid  = tid >> 5;
    const int lane = tid & 31;
    const int wm   = wid >> 1;
    const int wn   = wid & 1;
    const int bm = blockIdx.y, bn = blockIdx.x;

    const __half* Ab = A + (size_t)(bm * 128) * K;
    const __half* Bb = B + (size_t)(bn * 64) * K;

    const uint32_t sb = smem_u32(g_dsmem);

    float acc[4][4][4];
#pragma unroll
    for (int i = 0; i < 4; i++)
#pragma unroll
        for (int j = 0; j < 4; j++)
#pragma unroll
            for (int v = 0; v < 4; v++) acc[i][j][v] = 0.0f;

    const int NS = K >> 6;

    auto load_stage = [&](int s, int buf) {
        const int k0 = s << 6;
        const uint32_t base = sb + buf * G6STAGE;
#pragma unroll
        for (int i = 0; i < 8; i++) {
            const int idx = i * 128 + tid;
            const int r = idx >> 3, c = idx & 7;
            CP_ASYNC16(base + r * GROWB + c * 16, Ab + (size_t)r * K + k0 + c * 8);
        }
#pragma unroll
        for (int i = 0; i < 4; i++) {
            const int idx = i * 128 + tid;
            const int r = idx >> 3, c = idx & 7;
            CP_ASYNC16(base + G6ATILE + r * GROWB + c * 16, Bb + (size_t)r * K + k0 + c * 8);
        }
        CP_COMMIT();
    };

    load_stage(0, 0);

    const int a_row  = (lane & 15);
    const int a_koff = (lane >> 4) * 16;
    const int b_blk  = lane >> 3;
    const int b_row8 = lane & 7;
    const int b_noff = ((b_blk >> 1) << 3) + b_row8;
    const int b_koff = (b_blk & 1) * 16;

    for (int s = 0; s < NS; s++) {
        CP_WAIT0();
        __syncthreads();
        if (s + 1 < NS) load_stage(s + 1, (s + 1) & 1);

        const uint32_t st = sb + (s & 1) * G6STAGE;
#pragma unroll
        for (int ks = 0; ks < 4; ks++) {
            const int kb = ks * 32;

            uint32_t af[4][4], bf[4][2];
#pragma unroll
            for (int mt = 0; mt < 4; mt++) {
                const uint32_t ar = st + (wm * 64 + mt * 16 + a_row) * GROWB + kb + a_koff;
                LDMATRIX_X4(af[mt][0], af[mt][1], af[mt][2], af[mt][3], ar);
            }
#pragma unroll
            for (int p = 0; p < 2; p++) {
                const uint32_t br = st + G6ATILE +
                    (wn * 32 + p * 16 + b_noff) * GROWB + kb + b_koff;
                LDMATRIX_X4(bf[2 * p][0], bf[2 * p][1], bf[2 * p + 1][0], bf[2 * p + 1][1], br);
            }
#pragma unroll
            for (int mt = 0; mt < 4; mt++)
#pragma unroll
                for (int nt = 0; nt < 4; nt++)
                    MMA_F16(acc[mt][nt], af[mt], bf[nt]);
        }
    }

    const int r0 = bm * 128 + wm * 64 + (lane >> 2);
    const int c0 = bn * 64 + wn * 32 + (lane & 3) * 2;
#pragma unroll
    for (int mt = 0; mt < 4; mt++)
#pragma unroll
        for (int nt = 0; nt < 4; nt++) {
            const int row = r0 + mt * 16;
            const int col = c0 + nt * 8;
            const float b0 = bias[col], b1 = bias[col + 1];
            *(uint32_t*)(Ch + (size_t)row * N + col) =
                pack_f16(acc[mt][nt][0] * IWSC + b0, acc[mt][nt][1] * IWSC + b1);
            *(uint32_t*)(Ch + (size_t)(row + 8) * N + col) =
                pack_f16(acc[mt][nt][2] * IWSC + b0, acc[mt][nt][3] * IWSC + b1);
        }
}

// ---------------------------------------------------------------------------
// f16 HMMA GEMM v4 (proj, frozen): 128x128 CTA, 2 CTAs/SM, fp32 output.
// ---------------------------------------------------------------------------
#define GATILE (128 * GROWB)
#define GSTAGE (2 * GATILE)
#define GSMEM  (3 * GSTAGE)

__global__ void __launch_bounds__(128, 2) gemm_mma(
    const __half* __restrict__ A, const __half* __restrict__ B,
    const float* __restrict__ bias, float* __restrict__ Cf,
    int M, int N, int K)
{
    const int tid  = threadIdx.x;
    const int wid  = tid >> 5;
    const int lane = tid & 31;
    const int wm   = wid >> 1;
    const int wn   = wid & 1;
    const int bm = blockIdx.y, bn = blockIdx.x;

    const __half* Ab = A + (size_t)(bm * 128) * K;
    const __half* Bb = B + (size_t)(bn * 128) * K;

    const uint32_t sb = smem_u32(g_dsmem);

    float acc[4][8][4];
#pragma unroll
    for (int i = 0; i < 4; i++)
#pragma unroll
        for (int j = 0; j < 8; j++)
#pragma unroll
            for (int v = 0; v < 4; v++) acc[i][j][v] = 0.0f;

    const int NS = K >> 6;

    auto load_stage = [&](int s, int buf) {
        const int k0 = s << 6;
        const uint32_t base = sb + buf * GSTAGE;
#pragma unroll
        for (int i = 0; i < 8; i++) {
            const int idx = i * 128 + tid;
            const int r = idx >> 3, c = idx & 7;
            CP_ASYNC16(base + r * GROWB + c * 16, Ab + (size_t)r * K + k0 + c * 8);
        }
#pragma unroll
        for (int i = 0; i < 8; i++) {
            const int idx = i * 128 + tid;
            const int r = idx >> 3, c = idx & 7;
            CP_ASYNC16(base + GATILE + r * GROWB + c * 16, Bb + (size_t)r * K + k0 + c * 8);
        }
        CP_COMMIT();
    };

    load_stage(0, 0);
    load_stage(1, 1);

    const int a_row  = (lane & 15);
    const int a_koff = (lane >> 4) * 16;
    const int b_blk  = lane >> 3;
    const int b_row8 = lane & 7;
    const int b_noff = ((b_blk >> 1) << 3) + b_row8;
    const int b_koff = (b_blk & 1) * 16;

    for (int s = 0; s < NS; s++) {
        if (s < NS - 1) CP_WAIT1();
        else            CP_WAIT0();
        __syncthreads();
        if (s + 2 < NS) load_stage(s + 2, (s + 2) % 3);

        const uint32_t st = sb + (s % 3) * GSTAGE;
#pragma unroll
        for (int ks = 0; ks < 4; ks++) {
            const int kb = ks * 32;

            uint32_t af[4][4], bf[8][2];
#pragma unroll
            for (int mt = 0; mt < 4; mt++) {
                const uint32_t ar = st + (wm * 64 + mt * 16 + a_row) * GROWB + kb + a_koff;
                LDMATRIX_X4(af[mt][0], af[mt][1], af[mt][2], af[mt][3], ar);
            }
#pragma unroll
            for (int p = 0; p < 4; p++) {
                const uint32_t br = st + GATILE +
                    (wn * 64 + p * 16 + b_noff) * GROWB + kb + b_koff;
                LDMATRIX_X4(bf[2 * p][0], bf[2 * p][1], bf[2 * p + 1][0], bf[2 * p + 1][1], br);
            }
#pragma unroll
            for (int mt = 0; mt < 4; mt++)
#pragma unroll
                for (int nt = 0; nt < 8; nt++)
                    MMA_F16(acc[mt][nt], af[mt], bf[nt]);
        }
    }

    const int r0 = bm * 128 + wm * 64 + (lane >> 2);
    const int c0 = bn * 128 + wn * 64 + (lane & 3) * 2;
#pragma unroll
    for (int mt = 0; mt < 4; mt++)
#pragma unroll
        for (int nt = 0; nt < 8; nt++) {
            const int row = r0 + mt * 16;
            const int col = c0 + nt * 8;
            float2 o0, o1;
            o0.x = acc[mt][nt][0] * IWSC + bias[col];
            o0.y = acc[mt][nt][1] * IWSC + bias[col + 1];
            o1.x = acc[mt][nt][2] * IWSC + bias[col];
            o1.y = acc[mt][nt][3] * IWSC + bias[col + 1];
            *(float2*)(Cf + (size_t)row * N + col) = o0;
            *(float2*)(Cf + (size_t)(row + 8) * N + col) = o1;
        }
}

// ---------------------------------------------------------------------------
// Tensor-core causal flash attention v8: R15 structure + softmax denominator
// accumulated ON THE TENSOR CORE (P @ ones via one extra n8 MMA per k16 step).
// Removes per-tile fp32 l-sum adds and the end-of-kernel shfl reduction;
// l is numerically consistent with the PV numerator (same f16 P).
// 4 warps x 16 q-rows, 64-key tiles, base-2 softmax, alpha-skip, 4 CTAs/SM.
// ---------------------------------------------------------------------------
#define AROWB 144
#define ATILE (64 * AROWB)
#define ASTAGE (2 * ATILE)
#define ASMEM (3 * ASTAGE)

__global__ void __launch_bounds__(128, 4) attn_mma(
    const __half* __restrict__ QKV, __half* __restrict__ O)
{
    const int tid  = threadIdx.x;
    const int wid  = tid >> 5;
    const int lane = tid & 31;
    const int qtile = (gridDim.x - 1) - blockIdx.x;   // heavy tiles first
    const int bh = blockIdx.y;
    const int b  = bh >> 4;
    const int h  = bh & 15;
    const int bS = b * SS;
    const int qrow0 = qtile * 64;
    const int qbase = qrow0 + wid * 16;

    const uint32_t sb = smem_u32(g_dsmem);

    // stage Q (64 rows x 64 dims f16)
#pragma unroll
    for (int i = 0; i < 4; i++) {
        const int idx = i * 128 + tid;
        const int r = idx >> 3, c = idx & 7;
        const size_t g = (size_t)(bS + qrow0 + r) * D3 + h * HD + c * 8;
        CP_ASYNC16(sb + r * AROWB + c * 16, QKV + g);
    }
    CP_COMMIT();
    CP_WAIT0();
    __syncthreads();

    // Q fragments, pre-scaled by 0.125*log2(e)
    uint32_t qf[4][4];
    const int a_row  = lane & 15;
    const int a_koff = (lane >> 4) * 16;
    {
        const uint32_t qr = sb + (wid * 16 + a_row) * AROWB + a_koff;
        const __half2 qs = __float2half2_rn(QSCALE);
#pragma unroll
        for (int ks = 0; ks < 4; ks++) {
            LDMATRIX_X4(qf[ks][0], qf[ks][1], qf[ks][2], qf[ks][3], qr + ks * 32);
#pragma unroll
            for (int j = 0; j < 4; j++) {
                __half2 v = *reinterpret_cast<__half2*>(&qf[ks][j]);
                v = __hmul2(v, qs);
                qf[ks][j] = *reinterpret_cast<uint32_t*>(&v);
            }
        }
    }
    __syncthreads();

    auto load_kv = [&](int kt, int buf) {
        const int k0 = kt * 64;
        const uint32_t base = sb + buf * ASTAGE;
#pragma unroll
        for (int i = 0; i < 8; i++) {
            const int idx  = i * 128 + tid;
            const int tile = idx >> 9;
            const int r    = (idx >> 3) & 63;
            const int c    = idx & 7;
            const size_t g = (size_t)(bS + k0 + r) * D3 +
                             (tile ? 2 * DD : DD) + h * HD + c * 8;
            CP_ASYNC16(base + tile * ATILE + r * AROWB + c * 16, QKV + g);
        }
        CP_COMMIT();
    };

    float o[8][4];
#pragma unroll
    for (int n = 0; n < 8; n++)
#pragma unroll
        for (int j = 0; j < 4; j++) o[n][j] = 0.0f;
    float lacc[4] = {0.f, 0.f, 0.f, 0.f};     // row-sum accumulator (ones-MMA)
    float mrow[2] = {-1e30f, -1e30f};
    const uint32_t ones_b[2] = {0x3C003C00u, 0x3C003C00u};  // f16 1.0 x4

    const int b_blk  = lane >> 3;
    const int b_row8 = lane & 7;
    const int b_noff = ((b_blk >> 1) << 3) + b_row8;
    const int b_koff = (b_blk & 1) * 16;
    const int v_row  = lane & 15;
    const int v_coff = ((lane >> 4) & 1) * 16;

    const int ntl = qtile + 1;
    load_kv(0, 0);
    if (ntl > 1) load_kv(1, 1);

    for (int kt = 0; kt < ntl; kt++) {
        if (kt < ntl - 1) CP_WAIT1();
        else              CP_WAIT0();
        __syncthreads();
        if (kt + 2 < ntl) load_kv(kt + 2, (kt + 2) % 3);

        const int k0 = kt * 64;
        if (k0 <= qbase + 15) {
            const uint32_t kbse = sb + (kt % 3) * ASTAGE;
            const uint32_t vbse = kbse + ATILE;

            // S = Q K^T (base-2 logits)
            float s[8][4];
#pragma unroll
            for (int n = 0; n < 8; n++)
#pragma unroll
                for (int j = 0; j < 4; j++) s[n][j] = 0.0f;

#pragma unroll
            for (int p = 0; p < 4; p++) {
#pragma unroll
                for (int ks = 0; ks < 4; ks++) {
                    uint32_t kf[4];
                    const uint32_t ar = kbse + (p * 16 + b_noff) * AROWB + ks * 32 + b_koff;
                    LDMATRIX_X4(kf[0], kf[1], kf[2], kf[3], ar);
                    uint32_t b0[2] = {kf[0], kf[1]}, b1[2] = {kf[2], kf[3]};
                    MMA_F16(s[2 * p],     qf[ks], b0);
                    MMA_F16(s[2 * p + 1], qf[ks], b1);
                }
            }

            // masking + online softmax (base 2, alpha-skip); l via ones-MMA
            const bool need_mask = (k0 + 63 > qbase);
            const int row0 = qbase + (lane >> 2);
            const int colb = k0 + (lane & 3) * 2;
#pragma unroll
            for (int hf = 0; hf < 2; hf++) {
                const int row = row0 + 8 * hf;
                float mx = mrow[hf];
                if (need_mask) {
#pragma unroll
                    for (int n = 0; n < 8; n++) {
                        const int col = colb + 8 * n;
                        if (col > row)     s[n][2 * hf]     = -1e30f;
                        if (col + 1 > row) s[n][2 * hf + 1] = -1e30f;
                    }
                }
#pragma unroll
                for (int n = 0; n < 8; n++)
                    mx = fmaxf(mx, fmaxf(s[n][2 * hf], s[n][2 * hf + 1]));
                mx = fmaxf(mx, __shfl_xor_sync(0xffffffffu, mx, 1));
                mx = fmaxf(mx, __shfl_xor_sync(0xffffffffu, mx, 2));
                if (mx > mrow[hf]) {
                    const float alpha = ex2(mrow[hf] - mx);
                    lacc[2 * hf]     *= alpha;
                    lacc[2 * hf + 1] *= alpha;
#pragma unroll
                    for (int n = 0; n < 8; n++) {
                        o[n][2 * hf]     *= alpha;
                        o[n][2 * hf + 1] *= alpha;
                    }
                    mrow[hf] = mx;
                }
#pragma unroll
                for (int n = 0; n < 8; n++) {
                    s[n][2 * hf]     = ex2(s[n][2 * hf]     - mx);
                    s[n][2 * hf + 1] = ex2(s[n][2 * hf + 1] - mx);
                }
            }

            // O += P V ; l += P @ ones (tensor core)
#pragma unroll
            for (int ks = 0; ks < 4; ks++) {
                uint32_t pf[4];
#pragma unroll
                for (int q2 = 0; q2 < 2; q2++) {
                    const float* pv = s[2 * ks + q2];
                    pf[q2 * 2]     = pack_f16(pv[0], pv[1]);
                    pf[q2 * 2 + 1] = pack_f16(pv[2], pv[3]);
                }
                MMA_F16(lacc, pf, ones_b);   // row sums (all 4 cols identical)
#pragma unroll
                for (int np = 0; np < 4; np++) {
                    uint32_t vf[4];
                    const uint32_t va = vbse + (ks * 16 + v_row) * AROWB + np * 32 + v_coff;
                    LDMATRIX_X4_T(vf[0], vf[1], vf[2], vf[3], va);
                    uint32_t v0[2] = {vf[0], vf[1]}, v1[2] = {vf[2], vf[3]};
                    MMA_F16(o[2 * np],     pf, v0);
                    MMA_F16(o[2 * np + 1], pf, v1);
                }
            }
        }
    }

    // finalize: lacc[0] = row sum (hf0), lacc[2] = row sum (hf1); no shfl needed
    const float inv0 = 1.0f / lacc[0];
    const float inv1 = 1.0f / lacc[2];
    const int row0 = qbase + (lane >> 2);
    const int colb = h * HD + (lane & 3) * 2;
    {
        const size_t rof0 = (size_t)(bS + row0) * DD;
        const size_t rof1 = (size_t)(bS + row0 + 8) * DD;
#pragma unroll
        for (int n = 0; n < 8; n++) {
            *(uint32_t*)(O + rof0 + colb + n * 8) =
                pack_f16(o[n][0] * inv0, o[n][1] * inv0);
            *(uint32_t*)(O + rof1 + colb + n * 8) =
                pack_f16(o[n][2] * inv1, o[n][3] * inv1);
        }
    }
}

// ---------------------------------------------------------------------------
extern "C" void kernel_launch(void* const* d_in, const int* in_sizes, int n_in,
                              void* d_out, int out_size)
{
    const float* hidden   = (const float*)d_in[0];
    const float* c_attn_w = (const float*)d_in[1];
    const float* c_attn_b = (const float*)d_in[2];
    const float* c_proj_w = (const float*)d_in[3];
    const float* c_proj_b = (const float*)d_in[4];
    float* out = (float*)d_out;

    __half *qkv, *x, *a, *wq, *wp;
    cudaGetSymbolAddress((void**)&qkv, g_qkv);
    cudaGetSymbolAddress((void**)&x,   g_x);
    cudaGetSymbolAddress((void**)&a,   g_a);
    cudaGetSymbolAddress((void**)&wq,  g_wq);
    cudaGetSymbolAddress((void**)&wp,  g_wp);

    cudaFuncSetAttribute(gemm_mma64, cudaFuncAttributeMaxDynamicSharedMemorySize, G6SMEM);
    cudaFuncSetAttribute(gemm_mma,   cudaFuncAttributeMaxDynamicSharedMemorySize, GSMEM);
    cudaFuncSetAttribute(attn_mma,   cudaFuncAttributeMaxDynamicSharedMemorySize, ASMEM);

    // prep: one fused launch
    prep_all<<<NACT + 4096, 256>>>((const float4*)hidden, (uint2*)x,
                                   c_attn_w, wq, c_proj_w, wp);

    // 1) QKV projection -> f16
    gemm_mma64<<<dim3(D3 / 64, NT / 128), 128, G6SMEM>>>(
        x, wq, c_attn_b, qkv, NT, D3, DD);

    // 2) causal flash attention -> f16 (64 q-rows/CTA, 4 CTAs/SM, l via MMA)
    attn_mma<<<dim3(SS / 64, BB * HH), 128, ASMEM>>>(qkv, a);

    // 3) output projection -> fp32
    gemm_mma<<<dim3(DD / 128, NT / 128), 128, GSMEM>>>(
        a, wp, c_proj_b, out, NT, DD, DD);
}

// round 17
// speedup vs baseline: 1.0597x; 1.0081x over previous
#include <cuda_runtime.h>
#include <cuda_fp16.h>
#include <cstdint>

// Problem constants
#define BB 4
#define SS 2048
#define DD 1024
#define HH 16
#define HD 64
#define NT (BB * SS)        // 8192 tokens
#define D3 (3 * DD)         // 3072

#define WSC 64.0f           // weight scale 2^6
#define IWSC (1.0f / 64.0f)
#define QSCALE 0.1803368801f   // 0.125 * log2(e)

// ---------------------------------------------------------------------------
// Scratch (device globals — no runtime allocation)
// ---------------------------------------------------------------------------
static __device__ __half g_qkv[(size_t)NT * D3];
static __device__ __half g_x  [(size_t)NT * DD];
static __device__ __half g_a  [(size_t)NT * DD];
static __device__ __half g_wq [(size_t)D3 * DD];   // c_attn_w^T *64 [N][K]
static __device__ __half g_wp [(size_t)DD * DD];

// ---------------------------------------------------------------------------
__device__ __forceinline__ uint32_t smem_u32(const void* p) {
    uint32_t a;
    asm("{ .reg .u64 t; cvta.to.shared.u64 t, %1; cvt.u32.u64 %0, t; }" : "=r"(a) : "l"(p));
    return a;
}
__device__ __forceinline__ float ex2(float x) {
    float r;
    asm("ex2.approx.f32 %0, %1;" : "=f"(r) : "f"(x));
    return r;
}
__device__ __forceinline__ uint32_t ex2_f16x2(uint32_t x) {
    uint32_t r;
    asm("ex2.approx.f16x2 %0, %1;" : "=r"(r) : "r"(x));
    return r;
}

#define CP_ASYNC16(saddr, gptr) \
    asm volatile("cp.async.cg.shared.global [%0], [%1], 16;" :: "r"(saddr), "l"(gptr) : "memory")
#define CP_COMMIT()  asm volatile("cp.async.commit_group;" ::: "memory")
#define CP_WAIT0()   asm volatile("cp.async.wait_group 0;" ::: "memory")
#define CP_WAIT1()   asm volatile("cp.async.wait_group 1;" ::: "memory")

#define LDMATRIX_X4(r0, r1, r2, r3, addr) \
    asm volatile("ldmatrix.sync.aligned.m8n8.x4.shared.b16 {%0,%1,%2,%3}, [%4];" \
        : "=r"(r0), "=r"(r1), "=r"(r2), "=r"(r3) : "r"(addr))

#define LDMATRIX_X4_T(r0, r1, r2, r3, addr) \
    asm volatile("ldmatrix.sync.aligned.m8n8.x4.trans.shared.b16 {%0,%1,%2,%3}, [%4];" \
        : "=r"(r0), "=r"(r1), "=r"(r2), "=r"(r3) : "r"(addr))

#define MMA_F16(c, a, b) \
    asm volatile("mma.sync.aligned.m16n8k16.row.col.f32.f16.f16.f32 " \
        "{%0,%1,%2,%3}, {%4,%5,%6,%7}, {%8,%9}, {%0,%1,%2,%3};" \
        : "+f"((c)[0]), "+f"((c)[1]), "+f"((c)[2]), "+f"((c)[3]) \
        : "r"((a)[0]), "r"((a)[1]), "r"((a)[2]), "r"((a)[3]), "r"((b)[0]), "r"((b)[1]))

__device__ __forceinline__ uint32_t pack_f16(float a, float b) {
    __half2 t = __floats2half2_rn(a, b);
    return *reinterpret_cast<uint32_t*>(&t);
}

// ---------------------------------------------------------------------------
// Fused prep: activations -> f16, both weight transposes. One launch.
// ---------------------------------------------------------------------------
#define NACT 2048

__global__ void prep_all(const float4* __restrict__ x, uint2* __restrict__ xo,
                         const float* __restrict__ Wq, __half* __restrict__ oq,
                         const float* __restrict__ Wp, __half* __restrict__ op_) {
    const int blk = blockIdx.x;
    if (blk < NACT) {
        const int base = blk * 1024;
#pragma unroll
        for (int i = 0; i < 4; i++) {
            const int idx = base + i * 256 + threadIdx.x;
            float4 v = x[idx];
            uint2 r;
            r.x = pack_f16(v.x, v.y);
            r.y = pack_f16(v.z, v.w);
            xo[idx] = r;
        }
        return;
    }
    __shared__ float t[32][33];
    int wblk = blk - NACT;
    const int K = DD;
    int bx = wblk & 127;
    const int kb = (wblk >> 7) * 32;
    const float* W;
    __half* o;
    int N;
    if (bx < 96) { W = Wq; o = oq; N = D3; }
    else         { W = Wp; o = op_; N = DD; bx -= 96; }
    const int nb = bx * 32;
    const int tx = threadIdx.x & 31, ty = threadIdx.x >> 5;
#pragma unroll
    for (int i = 0; i < 32; i += 8)
        t[ty + i][tx] = W[(size_t)(kb + ty + i) * N + nb + tx];
    __syncthreads();
#pragma unroll
    for (int i = 0; i < 32; i += 8)
        o[(size_t)(nb + ty + i) * K + kb + tx] = __float2half_rn(t[tx][ty + i] * WSC);
}

// ---------------------------------------------------------------------------
// f16 HMMA GEMM v5 (QKV, frozen): 128x64 CTA, 3 CTAs/SM.
// ---------------------------------------------------------------------------
#define GROWB 144
#define G6ATILE (128 * GROWB)
#define G6BTILE (64 * GROWB)
#define G6STAGE (G6ATILE + G6BTILE)
#define G6SMEM  (2 * G6STAGE)

extern __shared__ char g_dsmem[];

__global__ void __launch_bounds__(128, 3) gemm_mma64(
    const __half* __restrict__ A, const __half* __restrict__ B,
    const float* __restrict__ bias, __half* __restrict__ Ch,
    int M, int N, int K)
{
    const int tid  = threadIdx.x;
    const int wid  = tid >> 5;
    const int lane = tid & 31;
    const int wm   = wid >> 1;
    const int wn   = wid & 1;
    const int bm = blockIdx.y, bn = blockIdx.x;

    const __half* Ab = A + (size_t)(bm * 128) * K;
    const __half* Bb = B + (size_t)(bn * 64) * K;

    const uint32_t sb = smem_u32(g_dsmem);

    float acc[4][4][4];
#pragma unroll
    for (int i = 0; i < 4; i++)
#pragma unroll
        for (int j = 0; j < 4; j++)
#pragma unroll
            for (int v = 0; v < 4; v++) acc[i][j][v] = 0.0f;

    const int NS = K >> 6;

    auto load_stage = [&](int s, int buf) {
        const int k0 = s << 6;
        const uint32_t base = sb + buf * G6STAGE;
#pragma unroll
        for (int i = 0; i < 8; i++) {
            const int idx = i * 128 + tid;
            const int r = idx >> 3, c = idx & 7;
            CP_ASYNC16(base + r * GROWB + c * 16, Ab + (size_t)r * K + k0 + c * 8);
        }
#pragma unroll
        for (int i = 0; i < 4; i++) {
            const int idx = i * 128 + tid;
            const int r = idx >> 3, c = idx & 7;
            CP_ASYNC16(base + G6ATILE + r * GROWB + c * 16, Bb + (size_t)r * K + k0 + c * 8);
        }
        CP_COMMIT();
    };

    load_stage(0, 0);

    const int a_row  = (lane & 15);
    const int a_koff = (lane >> 4) * 16;
    const int b_blk  = lane >> 3;
    const int b_row8 = lane & 7;
    const int b_noff = ((b_blk >> 1) << 3) + b_row8;
    const int b_koff = (b_blk & 1) * 16;

    for (int s = 0; s < NS; s++) {
        CP_WAIT0();
        __syncthreads();
        if (s + 1 < NS) load_stage(s + 1, (s + 1) & 1);

        const uint32_t st = sb + (s & 1) * G6STAGE;
#pragma unroll
        for (int ks = 0; ks < 4; ks++) {
            const int kb = ks * 32;

            uint32_t af[4][4], bf[4][2];
#pragma unroll
            for (int mt = 0; mt < 4; mt++) {
                const uint32_t ar = st + (wm * 64 + mt * 16 + a_row) * GROWB + kb + a_koff;
                LDMATRIX_X4(af[mt][0], af[mt][1], af[mt][2], af[mt][3], ar);
            }
#pragma unroll
            for (int p = 0; p < 2; p++) {
                const uint32_t br = st + G6ATILE +
                    (wn * 32 + p * 16 + b_noff) * GROWB + kb + b_koff;
                LDMATRIX_X4(bf[2 * p][0], bf[2 * p][1], bf[2 * p + 1][0], bf[2 * p + 1][1], br);
            }
#pragma unroll
            for (int mt = 0; mt < 4; mt++)
#pragma unroll
                for (int nt = 0; nt < 4; nt++)
                    MMA_F16(acc[mt][nt], af[mt], bf[nt]);
        }
    }

    const int r0 = bm * 128 + wm * 64 + (lane >> 2);
    const int c0 = bn * 64 + wn * 32 + (lane & 3) * 2;
#pragma unroll
    for (int mt = 0; mt < 4; mt++)
#pragma unroll
        for (int nt = 0; nt < 4; nt++) {
            const int row = r0 + mt * 16;
            const int col = c0 + nt * 8;
            const float b0 = bias[col], b1 = bias[col + 1];
            *(uint32_t*)(Ch + (size_t)row * N + col) =
                pack_f16(acc[mt][nt][0] * IWSC + b0, acc[mt][nt][1] * IWSC + b1);
            *(uint32_t*)(Ch + (size_t)(row + 8) * N + col) =
                pack_f16(acc[mt][nt][2] * IWSC + b0, acc[mt][nt][3] * IWSC + b1);
        }
}

// ---------------------------------------------------------------------------
// f16 HMMA GEMM v4 (proj, frozen): 128x128 CTA, 2 CTAs/SM, fp32 output.
// ---------------------------------------------------------------------------
#define GATILE (128 * GROWB)
#define GSTAGE (2 * GATILE)
#define GSMEM  (3 * GSTAGE)

__global__ void __launch_bounds__(128, 2) gemm_mma(
    const __half* __restrict__ A, const __half* __restrict__ B,
    const float* __restrict__ bias, float* __restrict__ Cf,
    int M, int N, int K)
{
    const int tid  = threadIdx.x;
    const int wid  = tid >> 5;
    const int lane = tid & 31;
    const int wm   = wid >> 1;
    const int wn   = wid & 1;
    const int bm = blockIdx.y, bn = blockIdx.x;

    const __half* Ab = A + (size_t)(bm * 128) * K;
    const __half* Bb = B + (size_t)(bn * 128) * K;

    const uint32_t sb = smem_u32(g_dsmem);

    float acc[4][8][4];
#pragma unroll
    for (int i = 0; i < 4; i++)
#pragma unroll
        for (int j = 0; j < 8; j++)
#pragma unroll
            for (int v = 0; v < 4; v++) acc[i][j][v] = 0.0f;

    const int NS = K >> 6;

    auto load_stage = [&](int s, int buf) {
        const int k0 = s << 6;
        const uint32_t base = sb + buf * GSTAGE;
#pragma unroll
        for (int i = 0; i < 8; i++) {
            const int idx = i * 128 + tid;
            const int r = idx >> 3, c = idx & 7;
            CP_ASYNC16(base + r * GROWB + c * 16, Ab + (size_t)r * K + k0 + c * 8);
        }
#pragma unroll
        for (int i = 0; i < 8; i++) {
            const int idx = i * 128 + tid;
            const int r = idx >> 3, c = idx & 7;
            CP_ASYNC16(base + GATILE + r * GROWB + c * 16, Bb + (size_t)r * K + k0 + c * 8);
        }
        CP_COMMIT();
    };

    load_stage(0, 0);
    load_stage(1, 1);

    const int a_row  = (lane & 15);
    const int a_koff = (lane >> 4) * 16;
    const int b_blk  = lane >> 3;
    const int b_row8 = lane & 7;
    const int b_noff = ((b_blk >> 1) << 3) + b_row8;
    const int b_koff = (b_blk & 1) * 16;

    for (int s = 0; s < NS; s++) {
        if (s < NS - 1) CP_WAIT1();
        else            CP_WAIT0();
        __syncthreads();
        if (s + 2 < NS) load_stage(s + 2, (s + 2) % 3);

        const uint32_t st = sb + (s % 3) * GSTAGE;
#pragma unroll
        for (int ks = 0; ks < 4; ks++) {
            const int kb = ks * 32;

            uint32_t af[4][4], bf[8][2];
#pragma unroll
            for (int mt = 0; mt < 4; mt++) {
                const uint32_t ar = st + (wm * 64 + mt * 16 + a_row) * GROWB + kb + a_koff;
                LDMATRIX_X4(af[mt][0], af[mt][1], af[mt][2], af[mt][3], ar);
            }
#pragma unroll
            for (int p = 0; p < 4; p++) {
                const uint32_t br = st + GATILE +
                    (wn * 64 + p * 16 + b_noff) * GROWB + kb + b_koff;
                LDMATRIX_X4(bf[2 * p][0], bf[2 * p][1], bf[2 * p + 1][0], bf[2 * p + 1][1], br);
            }
#pragma unroll
            for (int mt = 0; mt < 4; mt++)
#pragma unroll
                for (int nt = 0; nt < 8; nt++)
                    MMA_F16(acc[mt][nt], af[mt], bf[nt]);
        }
    }

    const int r0 = bm * 128 + wm * 64 + (lane >> 2);
    const int c0 = bn * 128 + wn * 64 + (lane & 3) * 2;
#pragma unroll
    for (int mt = 0; mt < 4; mt++)
#pragma unroll
        for (int nt = 0; nt < 8; nt++) {
            const int row = r0 + mt * 16;
            const int col = c0 + nt * 8;
            float2 o0, o1;
            o0.x = acc[mt][nt][0] * IWSC + bias[col];
            o0.y = acc[mt][nt][1] * IWSC + bias[col + 1];
            o1.x = acc[mt][nt][2] * IWSC + bias[col];
            o1.y = acc[mt][nt][3] * IWSC + bias[col + 1];
            *(float2*)(Cf + (size_t)row * N + col) = o0;
            *(float2*)(Cf + (size_t)(row + 8) * N + col) = o1;
        }
}

// ---------------------------------------------------------------------------
// Tensor-core causal flash attention v9: R16 structure + fused pack+exp
// (ex2.approx.f16x2 produces PV A-fragments directly; EX2 count halved,
// PV pack pass deleted). l still via ones-MMA on the same f16 P.
// 4 warps x 16 q-rows, 64-key tiles, alpha-skip, 4 CTAs/SM.
// ---------------------------------------------------------------------------
#define AROWB 144
#define ATILE (64 * AROWB)
#define ASTAGE (2 * ATILE)
#define ASMEM (3 * ASTAGE)

__global__ void __launch_bounds__(128, 4) attn_mma(
    const __half* __restrict__ QKV, __half* __restrict__ O)
{
    const int tid  = threadIdx.x;
    const int wid  = tid >> 5;
    const int lane = tid & 31;
    const int qtile = (gridDim.x - 1) - blockIdx.x;   // heavy tiles first
    const int bh = blockIdx.y;
    const int b  = bh >> 4;
    const int h  = bh & 15;
    const int bS = b * SS;
    const int qrow0 = qtile * 64;
    const int qbase = qrow0 + wid * 16;

    const uint32_t sb = smem_u32(g_dsmem);

    // stage Q (64 rows x 64 dims f16)
#pragma unroll
    for (int i = 0; i < 4; i++) {
        const int idx = i * 128 + tid;
        const int r = idx >> 3, c = idx & 7;
        const size_t g = (size_t)(bS + qrow0 + r) * D3 + h * HD + c * 8;
        CP_ASYNC16(sb + r * AROWB + c * 16, QKV + g);
    }
    CP_COMMIT();
    CP_WAIT0();
    __syncthreads();

    // Q fragments, pre-scaled by 0.125*log2(e)
    uint32_t qf[4][4];
    const int a_row  = lane & 15;
    const int a_koff = (lane >> 4) * 16;
    {
        const uint32_t qr = sb + (wid * 16 + a_row) * AROWB + a_koff;
        const __half2 qs = __float2half2_rn(QSCALE);
#pragma unroll
        for (int ks = 0; ks < 4; ks++) {
            LDMATRIX_X4(qf[ks][0], qf[ks][1], qf[ks][2], qf[ks][3], qr + ks * 32);
#pragma unroll
            for (int j = 0; j < 4; j++) {
                __half2 v = *reinterpret_cast<__half2*>(&qf[ks][j]);
                v = __hmul2(v, qs);
                qf[ks][j] = *reinterpret_cast<uint32_t*>(&v);
            }
        }
    }
    __syncthreads();

    auto load_kv = [&](int kt, int buf) {
        const int k0 = kt * 64;
        const uint32_t base = sb + buf * ASTAGE;
#pragma unroll
        for (int i = 0; i < 8; i++) {
            const int idx  = i * 128 + tid;
            const int tile = idx >> 9;
            const int r    = (idx >> 3) & 63;
            const int c    = idx & 7;
            const size_t g = (size_t)(bS + k0 + r) * D3 +
                             (tile ? 2 * DD : DD) + h * HD + c * 8;
            CP_ASYNC16(base + tile * ATILE + r * AROWB + c * 16, QKV + g);
        }
        CP_COMMIT();
    };

    float o[8][4];
#pragma unroll
    for (int n = 0; n < 8; n++)
#pragma unroll
        for (int j = 0; j < 4; j++) o[n][j] = 0.0f;
    float lacc[4] = {0.f, 0.f, 0.f, 0.f};
    float mrow[2] = {-1e30f, -1e30f};
    const uint32_t ones_b[2] = {0x3C003C00u, 0x3C003C00u};

    const int b_blk  = lane >> 3;
    const int b_row8 = lane & 7;
    const int b_noff = ((b_blk >> 1) << 3) + b_row8;
    const int b_koff = (b_blk & 1) * 16;
    const int v_row  = lane & 15;
    const int v_coff = ((lane >> 4) & 1) * 16;

    const int ntl = qtile + 1;
    load_kv(0, 0);
    if (ntl > 1) load_kv(1, 1);

    for (int kt = 0; kt < ntl; kt++) {
        if (kt < ntl - 1) CP_WAIT1();
        else              CP_WAIT0();
        __syncthreads();
        if (kt + 2 < ntl) load_kv(kt + 2, (kt + 2) % 3);

        const int k0 = kt * 64;
        if (k0 <= qbase + 15) {
            const uint32_t kbse = sb + (kt % 3) * ASTAGE;
            const uint32_t vbse = kbse + ATILE;

            // S = Q K^T (base-2 logits)
            float s[8][4];
#pragma unroll
            for (int n = 0; n < 8; n++)
#pragma unroll
                for (int j = 0; j < 4; j++) s[n][j] = 0.0f;

#pragma unroll
            for (int p = 0; p < 4; p++) {
#pragma unroll
                for (int ks = 0; ks < 4; ks++) {
                    uint32_t kf[4];
                    const uint32_t ar = kbse + (p * 16 + b_noff) * AROWB + ks * 32 + b_koff;
                    LDMATRIX_X4(kf[0], kf[1], kf[2], kf[3], ar);
                    uint32_t b0[2] = {kf[0], kf[1]}, b1[2] = {kf[2], kf[3]};
                    MMA_F16(s[2 * p],     qf[ks], b0);
                    MMA_F16(s[2 * p + 1], qf[ks], b1);
                }
            }

            // masking + online softmax (base 2, alpha-skip);
            // exp fused into the f16 pack: P fragments produced directly.
            uint32_t p16[8][2];
            const bool need_mask = (k0 + 63 > qbase);
            const int row0 = qbase + (lane >> 2);
            const int colb = k0 + (lane & 3) * 2;
#pragma unroll
            for (int hf = 0; hf < 2; hf++) {
                const int row = row0 + 8 * hf;
                float mx = mrow[hf];
                if (need_mask) {
#pragma unroll
                    for (int n = 0; n < 8; n++) {
                        const int col = colb + 8 * n;
                        if (col > row)     s[n][2 * hf]     = -1e30f;
                        if (col + 1 > row) s[n][2 * hf + 1] = -1e30f;
                    }
                }
#pragma unroll
                for (int n = 0; n < 8; n++)
                    mx = fmaxf(mx, fmaxf(s[n][2 * hf], s[n][2 * hf + 1]));
                mx = fmaxf(mx, __shfl_xor_sync(0xffffffffu, mx, 1));
                mx = fmaxf(mx, __shfl_xor_sync(0xffffffffu, mx, 2));
                if (mx > mrow[hf]) {
                    const float alpha = ex2(mrow[hf] - mx);
                    lacc[2 * hf]     *= alpha;
                    lacc[2 * hf + 1] *= alpha;
#pragma unroll
                    for (int n = 0; n < 8; n++) {
                        o[n][2 * hf]     *= alpha;
                        o[n][2 * hf + 1] *= alpha;
                    }
                    mrow[hf] = mx;
                }
#pragma unroll
                for (int n = 0; n < 8; n++)
                    p16[n][hf] = ex2_f16x2(
                        pack_f16(s[n][2 * hf] - mx, s[n][2 * hf + 1] - mx));
            }

            // O += P V ; l += P @ ones (fragments come straight from p16)
#pragma unroll
            for (int ks = 0; ks < 4; ks++) {
                uint32_t pf[4] = { p16[2 * ks][0], p16[2 * ks][1],
                                   p16[2 * ks + 1][0], p16[2 * ks + 1][1] };
                MMA_F16(lacc, pf, ones_b);
#pragma unroll
                for (int np = 0; np < 4; np++) {
                    uint32_t vf[4];
                    const uint32_t va = vbse + (ks * 16 + v_row) * AROWB + np * 32 + v_coff;
                    LDMATRIX_X4_T(vf[0], vf[1], vf[2], vf[3], va);
                    uint32_t v0[2] = {vf[0], vf[1]}, v1[2] = {vf[2], vf[3]};
                    MMA_F16(o[2 * np],     pf, v0);
                    MMA_F16(o[2 * np + 1], pf, v1);
                }
            }
        }
    }

    // finalize: lacc[0]/lacc[2] hold the row sums; no shfl reduction needed
    const float inv0 = 1.0f / lacc[0];
    const float inv1 = 1.0f / lacc[2];
    const int row0 = qbase + (lane >> 2);
    const int colb = h * HD + (lane & 3) * 2;
    {
        const size_t rof0 = (size_t)(bS + row0) * DD;
        const size_t rof1 = (size_t)(bS + row0 + 8) * DD;
#pragma unroll
        for (int n = 0; n < 8; n++) {
            *(uint32_t*)(O + rof0 + colb + n * 8) =
                pack_f16(o[n][0] * inv0, o[n][1] * inv0);
            *(uint32_t*)(O + rof1 + colb + n * 8) =
                pack_f16(o[n][2] * inv1, o[n][3] * inv1);
        }
    }
}

// ---------------------------------------------------------------------------
extern "C" void kernel_launch(void* const* d_in, const int* in_sizes, int n_in,
                              void* d_out, int out_size)
{
    const float* hidden   = (const float*)d_in[0];
    const float* c_attn_w = (const float*)d_in[1];
    const float* c_attn_b = (const float*)d_in[2];
    const float* c_proj_w = (const float*)d_in[3];
    const float* c_proj_b = (const float*)d_in[4];
    float* out = (float*)d_out;

    __half *qkv, *x, *a, *wq, *wp;
    cudaGetSymbolAddress((void**)&qkv, g_qkv);
    cudaGetSymbolAddress((void**)&x,   g_x);
    cudaGetSymbolAddress((void**)&a,   g_a);
    cudaGetSymbolAddress((void**)&wq,  g_wq);
    cudaGetSymbolAddress((void**)&wp,  g_wp);

    cudaFuncSetAttribute(gemm_mma64, cudaFuncAttributeMaxDynamicSharedMemorySize, G6SMEM);
    cudaFuncSetAttribute(gemm_mma,   cudaFuncAttributeMaxDynamicSharedMemorySize, GSMEM);
    cudaFuncSetAttribute(attn_mma,   cudaFuncAttributeMaxDynamicSharedMemorySize, ASMEM);

    // prep: one fused launch
    prep_all<<<NACT + 4096, 256>>>((const float4*)hidden, (uint2*)x,
                                   c_attn_w, wq, c_proj_w, wp);

    // 1) QKV projection -> f16
    gemm_mma64<<<dim3(D3 / 64, NT / 128), 128, G6SMEM>>>(
        x, wq, c_attn_b, qkv, NT, D3, DD);

    // 2) causal flash attention -> f16
    attn_mma<<<dim3(SS / 64, BB * HH), 128, ASMEM>>>(qkv, a);

    // 3) output projection -> fp32
    gemm_mma<<<dim3(DD / 128, NT / 128), 128, GSMEM>>>(
        a, wp, c_proj_b, out, NT, DD, DD);
}